// round 2
// baseline (speedup 1.0000x reference)
#include <cuda_runtime.h>
#include <stdint.h>

#define NB    32
#define CIN   256
#define HDIM  56
#define HW    3136            // 56*56
#define PIX   (NB*HW)         // 100352
#define OC    256
#define WORDS 8               // 256 channels / 32
#define TAPS  9
#define WPT   72              // TAPS*WORDS
#define KELEM 2304            // 256*9

// ---- device scratch (static allocation: allowed) ----
__device__ float    g_alpha[NB];
__device__ float    g_m[OC];
__device__ float    g_part[NB*16];
__device__ unsigned g_xbits[PIX*WORDS];     // [pixel][word]  ~3.2MB
__device__ unsigned g_wbits[OC*WPT];        // [o][tap][word] ~73.7KB
__device__ int      g_wpop[OC*TAPS];        // popc per (o,tap)

// ---------------------------------------------------------------------------
// 1) partial |x| sums: grid = 32*16 blocks, each block one (n, chunk)
// ---------------------------------------------------------------------------
__global__ void k_absmean_x(const float* __restrict__ x) {
    int n = blockIdx.x >> 4;
    int chunk = blockIdx.x & 15;
    // per-n: 802816 floats = 200704 float4; per chunk: 12544 float4
    const float4* xv = (const float4*)x + (size_t)n * 200704 + (size_t)chunk * 12544;
    float s = 0.f;
    for (int i = threadIdx.x; i < 12544; i += 256) {
        float4 v = xv[i];
        s += fabsf(v.x) + fabsf(v.y) + fabsf(v.z) + fabsf(v.w);
    }
    __shared__ float sh[8];
    #pragma unroll
    for (int d = 16; d > 0; d >>= 1) s += __shfl_down_sync(0xffffffffu, s, d);
    if ((threadIdx.x & 31) == 0) sh[threadIdx.x >> 5] = s;
    __syncthreads();
    if (threadIdx.x == 0) {
        float t = 0.f;
        #pragma unroll
        for (int i = 0; i < 8; i++) t += sh[i];
        g_part[blockIdx.x] = t;
    }
}

__global__ void k_alpha() {
    int n = threadIdx.x;                 // 32 threads
    float s = 0.f;
    #pragma unroll
    for (int i = 0; i < 16; i++) s += g_part[n * 16 + i];
    float a = 2.f * s / (float)(CIN * HW);
    g_alpha[n] = fmaxf(a, 1e-5f);
}

// ---------------------------------------------------------------------------
// 2) weight: per-o mean|w|, bit-pack (bit=1 iff w>0), per-tap popcounts
//    one block per output channel o
// ---------------------------------------------------------------------------
__global__ void k_quant_w(const float* __restrict__ wt) {
    int o = blockIdx.x;
    const float* wo = wt + (size_t)o * KELEM;
    float s = 0.f;
    for (int i = threadIdx.x; i < KELEM; i += 256) s += fabsf(wo[i]);
    __shared__ float sh[8];
    __shared__ unsigned pw[WPT];
    #pragma unroll
    for (int d = 16; d > 0; d >>= 1) s += __shfl_down_sync(0xffffffffu, s, d);
    if ((threadIdx.x & 31) == 0) sh[threadIdx.x >> 5] = s;
    __syncthreads();
    if (threadIdx.x == 0) {
        float t = 0.f;
        #pragma unroll
        for (int i = 0; i < 8; i++) t += sh[i];
        g_m[o] = t / (float)KELEM;
    }
    if (threadIdx.x < WPT) {
        int t = threadIdx.x / 8, c = threadIdx.x % 8;
        unsigned word = 0u;
        #pragma unroll
        for (int j = 0; j < 32; j++) {
            // OIHW: element index (c*32+j)*9 + t within this o
            if (wo[(c * 32 + j) * 9 + t] > 0.f) word |= (1u << j);
        }
        g_wbits[o * WPT + t * 8 + c] = word;
        pw[t * 8 + c] = (unsigned)__popc(word);
    }
    __syncthreads();
    if (threadIdx.x < TAPS) {
        int t = threadIdx.x;
        int acc = 0;
        #pragma unroll
        for (int c = 0; c < 8; c++) acc += (int)pw[t * 8 + c];
        g_wpop[o * TAPS + t] = acc;
    }
}

// ---------------------------------------------------------------------------
// 3) activation bit-pack: thread = (pixel, word). bit=1 iff x>0.
//    grid (PIX/256, 8)
// ---------------------------------------------------------------------------
__global__ void k_binx(const float* __restrict__ x) {
    int p = blockIdx.x * 256 + threadIdx.x;
    int c = blockIdx.y;
    int n = p / HW, hw = p - n * HW;
    const float* xp = x + ((size_t)(n * CIN + c * 32)) * HW + hw;
    unsigned word = 0u;
    #pragma unroll
    for (int j = 0; j < 32; j++) {
        if (xp[(size_t)j * HW] > 0.f) word |= (1u << j);
    }
    g_xbits[(size_t)p * WORDS + c] = word;
}

// ---------------------------------------------------------------------------
// 4) binary conv. Block = 256 pixels x 128 output channels (o-half in y).
//    Weight bits for 128 o's live in SMEM (broadcast LDS.128).
//    Pixel's 72 xbit words live in registers. Inner loop branch-free; border
//    taps corrected afterwards using precomputed popc(w).
// ---------------------------------------------------------------------------
__global__ void __launch_bounds__(256, 2) k_conv(float* __restrict__ out) {
    __shared__ unsigned ws[128 * WPT];   // 36864 B
    __shared__ int      wp[128 * TAPS];  //  4608 B
    __shared__ float    sm[128];

    int o0 = blockIdx.y * 128;
    for (int i = threadIdx.x; i < 128 * WPT; i += 256) ws[i] = g_wbits[o0 * WPT + i];
    for (int i = threadIdx.x; i < 128 * TAPS; i += 256) wp[i] = g_wpop[o0 * TAPS + i];
    if (threadIdx.x < 128) sm[threadIdx.x] = g_m[o0 + threadIdx.x];
    __syncthreads();

    int p = blockIdx.x * 256 + threadIdx.x;
    int n = p / HW, hw = p - n * HW;
    int h = hw / HDIM, w = hw - h * HDIM;

    unsigned xb[WPT];
    unsigned invmask = 0u;
    #pragma unroll
    for (int t = 0; t < TAPS; t++) {
        int hh = h + t / 3 - 1;
        int ww = w + t % 3 - 1;
        if (hh >= 0 && hh < HDIM && ww >= 0 && ww < HDIM) {
            const uint4* src = (const uint4*)&g_xbits[((size_t)(n * HW + hh * HDIM + ww)) * WORDS];
            uint4 a = src[0], b = src[1];
            xb[t * 8 + 0] = a.x; xb[t * 8 + 1] = a.y; xb[t * 8 + 2] = a.z; xb[t * 8 + 3] = a.w;
            xb[t * 8 + 4] = b.x; xb[t * 8 + 5] = b.y; xb[t * 8 + 6] = b.z; xb[t * 8 + 7] = b.w;
        } else {
            invmask |= (1u << t);
            #pragma unroll
            for (int c = 0; c < 8; c++) xb[t * 8 + c] = 0u;
        }
    }

    float alpha = g_alpha[n];
    float* op = out + ((size_t)n * OC + o0) * HW + hw;

    for (int o = 0; o < 128; o++) {
        const uint4* wr = (const uint4*)&ws[o * WPT];
        int acc = 0;
        #pragma unroll
        for (int q = 0; q < 18; q++) {
            uint4 v = wr[q];
            acc += __popc(xb[q * 4 + 0] ^ v.x) + __popc(xb[q * 4 + 1] ^ v.y)
                 + __popc(xb[q * 4 + 2] ^ v.z) + __popc(xb[q * 4 + 3] ^ v.w);
        }
        int dot = KELEM - 2 * acc;        // full 9-tap count (pads counted w/ xb=0)
        if (invmask) {
            unsigned mm = invmask;
            while (mm) {
                int t = __ffs(mm) - 1; mm &= mm - 1;
                dot -= (256 - 2 * wp[o * TAPS + t]);   // remove xb=0 tap's popc(w) term
            }
        }
        op[(size_t)o * HW] = alpha * sm[o] * (float)dot;
    }
}

// ---------------------------------------------------------------------------
extern "C" void kernel_launch(void* const* d_in, const int* in_sizes, int n_in,
                              void* d_out, int out_size) {
    const float* x  = (const float*)d_in[0];
    const float* wt = (const float*)d_in[1];
    float* out = (float*)d_out;

    k_absmean_x<<<NB * 16, 256>>>(x);
    k_alpha<<<1, 32>>>();
    k_quant_w<<<OC, 256>>>(wt);
    k_binx<<<dim3(PIX / 256, 8), 256>>>(x);
    k_conv<<<dim3(PIX / 256, 2), 256>>>(out);
}